// round 8
// baseline (speedup 1.0000x reference)
#include <cuda_runtime.h>
#include <math.h>

#define BSZ 64
#define TT  512
#define DA  16
#define DZ  32
#define KK  3
#define GG  12   // 4*H, H=3

// ---------------- scratch (device globals; no allocs allowed) ----------------
__device__ float g_xw0[(size_t)BSZ * TT * GG];
__device__ float g_alpha[(size_t)BSZ * TT * KK];
__device__ float g_muf[(size_t)TT * BSZ * DZ];
__device__ float g_mup[(size_t)TT * BSZ * DZ];
__device__ float g_sigf[(size_t)TT * BSZ * DZ * DZ];
__device__ float g_sigp[(size_t)TT * BSZ * DZ * DZ];

__device__ __forceinline__ float sigm(float x) { return 1.0f / (1.0f + expf(-x)); }

// ---- warp-0 shared-memory Gauss-Jordan, row-per-lane, deferred row scaling ----
// Inverts the leading NxN block of M in place (row stride LD floats).
// Lanes >= N idle but participate in __syncwarp. 0 block barriers.
template <int N, int LD>
__device__ __forceinline__ void warp_gj_smem(float* M, int lane) {
    const bool rowok = lane < N;
    float dinv = 1.0f;
#pragma unroll 1
    for (int p = 0; p < N; p++) {
        float pv = M[p * LD + p];
        float rpv = 1.0f / pv;
        float f = 0.0f;
        if (rowok && lane != p) f = M[lane * LD + p] * rpv;
        if (rowok && lane == p) dinv = rpv;
        __syncwarp();                       // reads of row p / col p done
        if (rowok && lane != p) {
#pragma unroll
            for (int j = 0; j < N; j++)
                if (j != p) M[lane * LD + j] -= f * M[p * LD + j];
            M[lane * LD + p] = -f;
        }
        if (rowok && lane == p) M[p * LD + p] = 1.0f;
        __syncwarp();                       // row updates visible for next pivot
    }
    if (rowok) {
#pragma unroll
        for (int j = 0; j < N; j++) M[lane * LD + j] *= dinv;
    }
    __syncwarp();
}

// ---------------- Kernel A0: input projection for LSTM layer 0 ----------------
__global__ void xw0_kernel(const float* __restrict__ a,
                           const float* __restrict__ Wih0,
                           const float* __restrict__ bih0,
                           const float* __restrict__ bhh0) {
    int idx = blockIdx.x * blockDim.x + threadIdx.x;
    if (idx >= BSZ * TT * GG) return;
    int j  = idx % GG;
    int bt = idx / GG;
    const float* ar = a + (size_t)bt * DA;
    const float* w  = Wih0 + j * DA;
    float s = bih0[j] + bhh0[j];
#pragma unroll
    for (int d = 0; d < DA; d++) s += ar[d] * w[d];
    g_xw0[idx] = s;
}

// ---------------- Kernel A1: sequential 2-layer LSTM + softmax ----------------
__global__ void lstm_kernel(const float* __restrict__ Whh0,
                            const float* __restrict__ Wih1,
                            const float* __restrict__ Whh1,
                            const float* __restrict__ bih1,
                            const float* __restrict__ bhh1) {
    __shared__ float whh0[GG][3], wih1[GG][3], whh1[GG][3], b1[GG];
    int tid = threadIdx.x;
    if (tid < 36) {
        whh0[tid / 3][tid % 3] = Whh0[tid];
        wih1[tid / 3][tid % 3] = Wih1[tid];
        whh1[tid / 3][tid % 3] = Whh1[tid];
    }
    if (tid < GG) b1[tid] = bih1[tid] + bhh1[tid];
    __syncthreads();

    int b = tid;
    if (b >= BSZ) return;
    float h0[3] = {0, 0, 0}, c0[3] = {0, 0, 0};
    float h1[3] = {0, 0, 0}, c1[3] = {0, 0, 0};
    const float* xw = g_xw0 + (size_t)b * TT * GG;
    float* al = g_alpha + (size_t)b * TT * KK;

    for (int t = 0; t < TT; t++) {
        float g[GG];
#pragma unroll
        for (int j = 0; j < GG; j++)
            g[j] = xw[t * GG + j] + whh0[j][0] * h0[0] + whh0[j][1] * h0[1] + whh0[j][2] * h0[2];
#pragma unroll
        for (int u = 0; u < 3; u++) {
            c0[u] = sigm(g[3 + u]) * c0[u] + sigm(g[u]) * tanhf(g[6 + u]);
            h0[u] = sigm(g[9 + u]) * tanhf(c0[u]);
        }
#pragma unroll
        for (int j = 0; j < GG; j++)
            g[j] = b1[j] + wih1[j][0] * h0[0] + wih1[j][1] * h0[1] + wih1[j][2] * h0[2]
                         + whh1[j][0] * h1[0] + whh1[j][1] * h1[1] + whh1[j][2] * h1[2];
#pragma unroll
        for (int u = 0; u < 3; u++) {
            c1[u] = sigm(g[3 + u]) * c1[u] + sigm(g[u]) * tanhf(g[6 + u]);
            h1[u] = sigm(g[9 + u]) * tanhf(c1[u]);
        }
        float m = fmaxf(h1[0], fmaxf(h1[1], h1[2]));
        float e0 = expf(h1[0] - m), e1 = expf(h1[1] - m), e2 = expf(h1[2] - m);
        float inv = 1.0f / (e0 + e1 + e2);
        al[t * KK + 0] = e0 * inv;
        al[t * KK + 1] = e1 * inv;
        al[t * KK + 2] = e2 * inv;
    }
}

// ---------------- Kernel B: forward Kalman filter (one CTA per batch, 256 thr) ---
__global__ void __launch_bounds__(256) fwd_kernel(const float* __restrict__ a,
                                                  const float* __restrict__ A,
                                                  const float* __restrict__ C,
                                                  const float* __restrict__ R,
                                                  const float* __restrict__ Q,
                                                  const float* __restrict__ mu0,
                                                  const float* __restrict__ sigma0) {
    const int b = blockIdx.x;
    const int tid = threadIdx.x;
    const int i8 = tid >> 3;            // 0..31
    const int q4 = (tid & 7) * 4;       // 0,4,...,28

    __shared__ __align__(16) float sAt[DZ][36], sAtT[DZ][36];
    __shared__ __align__(16) float sCt[DA][36];
    __shared__ __align__(16) float sCtT[DZ][20];
    __shared__ __align__(16) float sSigP[DZ][36], sSigN[DZ][36], sT[DZ][36], sQ[DZ][36];
    __shared__ __align__(16) float sM1[DZ][20], sKg[DZ][20];
    __shared__ __align__(16) float sAug[DA][36];   // [S | I] 16x32 (+pad)
    __shared__ float sR[DA][17];
    __shared__ float smu_f[DZ], smu_p[DZ], smu_new[DZ], sr[DA];

    // ---- init ----
    if (tid < DZ) { smu_f[tid] = mu0[tid]; smu_p[tid] = mu0[tid]; }
    {
        int e = tid * 4, ii = e >> 5, jj = e & 31;
        float4 s0 = ((const float4*)sigma0)[tid];
        *(float4*)&sSigP[ii][jj] = s0;
        float4 q0 = ((const float4*)Q)[tid];
        *(float4*)&sQ[ii][jj] = q0;
        sR[tid >> 4][tid & 15] = R[tid];
    }
    __syncthreads();

    for (int t = 0; t < TT; t++) {
        // P0: mixing (alpha via direct global loads, broadcast through L2)
        const size_t abase = ((size_t)b * TT + t) * KK;
        const float a0 = g_alpha[abase + 0];
        const float a1 = g_alpha[abase + 1];
        const float a2 = g_alpha[abase + 2];
        {
            const float4* A0 = (const float4*)A + (size_t)t * 256;
            const float4* A1 = A0 + (size_t)TT * 256;
            const float4* A2 = A1 + (size_t)TT * 256;
            float4 v0 = A0[tid], v1 = A1[tid], v2 = A2[tid];
            float4 m;
            m.x = a0 * v0.x + a1 * v1.x + a2 * v2.x;
            m.y = a0 * v0.y + a1 * v1.y + a2 * v2.y;
            m.z = a0 * v0.z + a1 * v1.z + a2 * v2.z;
            m.w = a0 * v0.w + a1 * v1.w + a2 * v2.w;
            int e = tid * 4, ii = e >> 5, jj = e & 31;
            *(float4*)&sAt[ii][jj] = m;
            sAtT[jj + 0][ii] = m.x; sAtT[jj + 1][ii] = m.y;
            sAtT[jj + 2][ii] = m.z; sAtT[jj + 3][ii] = m.w;
            if (tid < 128) {
                const float4* C0 = (const float4*)C + (size_t)t * 128;
                const float4* C1 = C0 + (size_t)TT * 128;
                const float4* C2 = C1 + (size_t)TT * 128;
                float4 w0 = C0[tid], w1 = C1[tid], w2 = C2[tid];
                float4 c;
                c.x = a0 * w0.x + a1 * w1.x + a2 * w2.x;
                c.y = a0 * w0.y + a1 * w1.y + a2 * w2.y;
                c.z = a0 * w0.z + a1 * w1.z + a2 * w2.z;
                c.w = a0 * w0.w + a1 * w1.w + a2 * w2.w;
                int ec = tid * 4, ic = ec >> 5, jc = ec & 31;
                *(float4*)&sCt[ic][jc] = c;
                sCtT[jc + 0][ic] = c.x; sCtT[jc + 1][ic] = c.y;
                sCtT[jc + 2][ic] = c.z; sCtT[jc + 3][ic] = c.w;
            }
        }
        __syncthreads();

        // P1: r = a - Ct mu_f ; M1 = sigP * CtT  (32x16)
        if (tid < DA) {
            float s = a[((size_t)b * TT + t) * DA + tid];
#pragma unroll
            for (int j = 0; j < DZ; j++) s -= sCt[tid][j] * smu_f[j];
            sr[tid] = s;
        }
        {
            int jj = (tid & 7) * 2;
            float s0 = 0.f, s1 = 0.f;
#pragma unroll
            for (int k = 0; k < DZ; k++) {
                float av = sSigP[i8][k];
                s0 += av * sCtT[k][jj];
                s1 += av * sCtT[k][jj + 1];
            }
            sM1[i8][jj] = s0; sM1[i8][jj + 1] = s1;
        }
        __syncthreads();

        // P2: S = Ct*M1 + R into Aug left, identity right
        {
            int i = tid >> 4, j = tid & 15;
            float s = sR[i][j];
#pragma unroll
            for (int k = 0; k < DZ; k++) s += sCt[i][k] * sM1[k][j];
            sAug[i][j] = s;
            sAug[i][DA + j] = (i == j) ? 1.f : 0.f;
        }
        __syncthreads();

        // GJ16: warp 0 inverts left 16x16 of sAug in place (0 block barriers)
        if (tid < 32) warp_gj_smem<DA, 36>(&sAug[0][0], tid);
        __syncthreads();

        // Kg = M1 * Sinv (Sinv now in LEFT half of sAug)
        {
            int jj = (tid & 7) * 2;
            float s0 = 0.f, s1 = 0.f;
#pragma unroll
            for (int k = 0; k < DA; k++) {
                float av = sM1[i8][k];
                s0 += av * sAug[k][jj];
                s1 += av * sAug[k][jj + 1];
            }
            sKg[i8][jj] = s0; sKg[i8][jj + 1] = s1;
        }
        __syncthreads();

        // T1 = Kg * Ct (32x32, K=16)
        {
            float4 acc = make_float4(0, 0, 0, 0);
#pragma unroll
            for (int k = 0; k < DA; k++) {
                float av = sKg[i8][k];
                float4 bv = *(const float4*)&sCt[k][q4];
                acc.x += av * bv.x; acc.y += av * bv.y;
                acc.z += av * bv.z; acc.w += av * bv.w;
            }
            *(float4*)&sT[i8][q4] = acc;
        }
        __syncthreads();

        const size_t sb = (size_t)t * BSZ + b;

        // P: signew = sigP - T1*sigP ; mu_new -> smu_f, g_muf
        {
            float4 acc = *(const float4*)&sSigP[i8][q4];
#pragma unroll
            for (int k = 0; k < DZ; k++) {
                float av = sT[i8][k];
                float4 bv = *(const float4*)&sSigP[k][q4];
                acc.x -= av * bv.x; acc.y -= av * bv.y;
                acc.z -= av * bv.z; acc.w -= av * bv.w;
            }
            *(float4*)&sSigN[i8][q4] = acc;
            *(float4*)&g_sigf[sb * (DZ * DZ) + i8 * DZ + q4] = acc;
        }
        if (tid < DZ) {
            float s = smu_p[tid];
#pragma unroll
            for (int j = 0; j < DA; j++) s += sKg[tid][j] * sr[j];
            smu_f[tid] = s;
            g_muf[sb * DZ + tid] = s;
        }
        __syncthreads();

        // P: T2 = At*signew ; mu_p = At*mu_new
        {
            float4 acc = make_float4(0, 0, 0, 0);
#pragma unroll
            for (int k = 0; k < DZ; k++) {
                float av = sAt[i8][k];
                float4 bv = *(const float4*)&sSigN[k][q4];
                acc.x += av * bv.x; acc.y += av * bv.y;
                acc.z += av * bv.z; acc.w += av * bv.w;
            }
            *(float4*)&sT[i8][q4] = acc;
        }
        if (tid < DZ) {
            float s = 0.f;
#pragma unroll
            for (int j = 0; j < DZ; j++) s += sAt[tid][j] * smu_f[j];
            smu_p[tid] = s;
            g_mup[sb * DZ + tid] = s;
        }
        __syncthreads();

        // P: sigp = T2*At^T + Q
        {
            float4 acc = *(const float4*)&sQ[i8][q4];
#pragma unroll
            for (int k = 0; k < DZ; k++) {
                float av = sT[i8][k];
                float4 bv = *(const float4*)&sAtT[k][q4];
                acc.x += av * bv.x; acc.y += av * bv.y;
                acc.z += av * bv.z; acc.w += av * bv.w;
            }
            *(float4*)&sSigP[i8][q4] = acc;
            *(float4*)&g_sigp[sb * (DZ * DZ) + i8 * DZ + q4] = acc;
        }
        __syncthreads();
    }
}

// ---------------- Kernel C: RTS backward smoother (one CTA per batch, 256 thr) ---
__global__ void __launch_bounds__(256) bwd_kernel(const float* __restrict__ A,
                                                  float* __restrict__ out) {
    const int b = blockIdx.x;
    const int tid = threadIdx.x;
    const int i8 = tid >> 3;
    const int q4 = (tid & 7) * 4;

    __shared__ __align__(16) float sAT[DZ][36];
    __shared__ __align__(16) float sSigF[DZ][36], sSigNc[DZ][36], sD[DZ][36];
    __shared__ __align__(16) float sU[DZ][36], sJ[DZ][36];
    __shared__ __align__(16) float sAug[DZ][68];  // [sig_p | I], stride 272B (16B-mult)
    __shared__ float sMuN[DZ], sMuD[DZ];

    // init t = T-1: smoothed == filtered
    {
        size_t sb = ((size_t)(TT - 1) * BSZ + b);
        size_t ob = ((size_t)b * TT + (TT - 1)) * (DZ + DZ * DZ);
        int e = tid * 4, ii = e >> 5, jj = e & 31;
        float4 v = ((const float4*)(g_sigf + sb * (DZ * DZ)))[tid];
        *(float4*)&sSigNc[ii][jj] = v;
        *(float4*)&out[ob + DZ + e] = v;
        if (tid < DZ) {
            float m = g_muf[sb * DZ + tid];
            sMuN[tid] = m;
            out[ob + tid] = m;
        }
    }
    __syncthreads();

    for (int t = TT - 2; t >= 0; t--) {
        const size_t sb = (size_t)t * BSZ + b;
        const size_t abase = ((size_t)b * TT + (t + 1)) * KK;
        const float a0 = g_alpha[abase + 0];
        const float a1 = g_alpha[abase + 1];
        const float a2 = g_alpha[abase + 2];

        // P0: mix A^T, load sigF, init Aug=[sigp|I], D = sigN - sigp, muD
        {
            const float4* A0 = (const float4*)A + (size_t)(t + 1) * 256;
            const float4* A1 = A0 + (size_t)TT * 256;
            const float4* A2 = A1 + (size_t)TT * 256;
            float4 v0 = A0[tid], v1 = A1[tid], v2 = A2[tid];
            int e = tid * 4, ii = e >> 5, jj = e & 31;
            sAT[jj + 0][ii] = a0 * v0.x + a1 * v1.x + a2 * v2.x;
            sAT[jj + 1][ii] = a0 * v0.y + a1 * v1.y + a2 * v2.y;
            sAT[jj + 2][ii] = a0 * v0.z + a1 * v1.z + a2 * v2.z;
            sAT[jj + 3][ii] = a0 * v0.w + a1 * v1.w + a2 * v2.w;

            float4 sf = ((const float4*)(g_sigf + sb * (DZ * DZ)))[tid];
            *(float4*)&sSigF[ii][jj] = sf;
            float4 sp = ((const float4*)(g_sigp + sb * (DZ * DZ)))[tid];
            *(float4*)&sAug[ii][jj] = sp;
            float4 id;
            id.x = (ii == jj + 0) ? 1.f : 0.f;
            id.y = (ii == jj + 1) ? 1.f : 0.f;
            id.z = (ii == jj + 2) ? 1.f : 0.f;
            id.w = (ii == jj + 3) ? 1.f : 0.f;
            *(float4*)&sAug[ii][DZ + jj] = id;
            float4 d;
            d.x = sSigNc[ii][jj + 0] - sp.x;
            d.y = sSigNc[ii][jj + 1] - sp.y;
            d.z = sSigNc[ii][jj + 2] - sp.z;
            d.w = sSigNc[ii][jj + 3] - sp.w;
            *(float4*)&sD[ii][jj] = d;
            if (tid < DZ) sMuD[tid] = sMuN[tid] - g_mup[sb * DZ + tid];
        }
        __syncthreads();

        // GJ32: warp 0 inverts left 32x32 of sAug in place (0 block barriers)
        if (tid < 32) warp_gj_smem<DZ, 68>(&sAug[0][0], tid);
        __syncthreads();

        // P1: U = sigF * A^T
        {
            float4 acc = make_float4(0, 0, 0, 0);
#pragma unroll
            for (int k = 0; k < DZ; k++) {
                float av = sSigF[i8][k];
                float4 bv = *(const float4*)&sAT[k][q4];
                acc.x += av * bv.x; acc.y += av * bv.y;
                acc.z += av * bv.z; acc.w += av * bv.w;
            }
            *(float4*)&sU[i8][q4] = acc;
        }
        __syncthreads();

        // J = U * Pinv (Pinv now in LEFT half of sAug)
        {
            float4 acc = make_float4(0, 0, 0, 0);
#pragma unroll
            for (int k = 0; k < DZ; k++) {
                float av = sU[i8][k];
                float4 bv = *(const float4*)&sAug[k][q4];
                acc.x += av * bv.x; acc.y += av * bv.y;
                acc.z += av * bv.z; acc.w += av * bv.w;
            }
            *(float4*)&sJ[i8][q4] = acc;
        }
        __syncthreads();

        // outputs + carry update
        {
            const size_t ob = ((size_t)b * TT + t) * (DZ + DZ * DZ);
            float4 acc = *(const float4*)&sSigF[i8][q4];
#pragma unroll
            for (int k = 0; k < DZ; k++) {
                float av = sJ[i8][k];
                float4 bv = *(const float4*)&sD[k][q4];
                acc.x += av * bv.x; acc.y += av * bv.y;
                acc.z += av * bv.z; acc.w += av * bv.w;
            }
            *(float4*)&sSigNc[i8][q4] = acc;
            *(float4*)&out[ob + DZ + i8 * DZ + q4] = acc;
            if (tid < DZ) {
                float s = g_muf[sb * DZ + tid];
#pragma unroll
                for (int k = 0; k < DZ; k++) s += sJ[tid][k] * sMuD[k];
                sMuN[tid] = s;
                out[ob + tid] = s;
            }
        }
        __syncthreads();
    }
}

// ---------------- launch ----------------
extern "C" void kernel_launch(void* const* d_in, const int* in_sizes, int n_in,
                              void* d_out, int out_size) {
    const float* a      = (const float*)d_in[0];
    const float* A      = (const float*)d_in[1];
    const float* C      = (const float*)d_in[2];
    const float* R      = (const float*)d_in[3];
    const float* Q      = (const float*)d_in[4];
    const float* mu0    = (const float*)d_in[5];
    const float* sigma0 = (const float*)d_in[6];
    const float* Wih0   = (const float*)d_in[7];
    const float* Whh0   = (const float*)d_in[8];
    const float* bih0   = (const float*)d_in[9];
    const float* bhh0   = (const float*)d_in[10];
    const float* Wih1   = (const float*)d_in[11];
    const float* Whh1   = (const float*)d_in[12];
    const float* bih1   = (const float*)d_in[13];
    const float* bhh1   = (const float*)d_in[14];
    float* out = (float*)d_out;

    int n0 = BSZ * TT * GG;
    xw0_kernel<<<(n0 + 255) / 256, 256>>>(a, Wih0, bih0, bhh0);
    lstm_kernel<<<1, 64>>>(Whh0, Wih1, Whh1, bih1, bhh1);
    fwd_kernel<<<BSZ, 256>>>(a, A, C, R, Q, mu0, sigma0);
    bwd_kernel<<<BSZ, 256>>>(A, out);
}

// round 9
// speedup vs baseline: 2.8263x; 2.8263x over previous
#include <cuda_runtime.h>
#include <math.h>

#define BSZ 64
#define TT  512
#define DA  16
#define DZ  32
#define KK  3
#define GG  12   // 4*H, H=3

// ---------------- scratch (device globals; no allocs allowed) ----------------
__device__ float g_xw0[(size_t)BSZ * TT * GG];
__device__ float g_alpha[(size_t)BSZ * TT * KK];
__device__ float g_muf[(size_t)TT * BSZ * DZ];
__device__ float g_mup[(size_t)TT * BSZ * DZ];
__device__ float g_sigf[(size_t)TT * BSZ * DZ * DZ];
__device__ float g_sigp[(size_t)TT * BSZ * DZ * DZ];

__device__ __forceinline__ float sigm(float x) { return 1.0f / (1.0f + expf(-x)); }

// ---- warp-0 register/shuffle Gauss-Jordan, row-per-lane, deferred scaling ----
// Inverts the leading NxN block of M in place (row stride LD floats).
// Same recurrence as the (passing) smem version; rows live in registers,
// pivot row broadcast via shuffle. 0 block barriers, 0 smem traffic inside.
template <int N, int LD>
__device__ __forceinline__ void warp_gj_reg(float* M, int lane) {
    const int i = (N == 32) ? lane : (lane & (N - 1));  // mirror rows if N<32
    float c[N];
#pragma unroll
    for (int j = 0; j < N; j++) c[j] = M[i * LD + j];
    float dinv = 1.0f;
#pragma unroll
    for (int p = 0; p < N; p++) {
        float pv = __shfl_sync(0xffffffffu, c[p], p);
        float rpv = 1.0f / pv;
        float f = (i == p) ? 0.0f : c[p] * rpv;
        if (i == p) dinv = rpv;
        float ncp = (i == p) ? 1.0f : -f;
#pragma unroll
        for (int j = 0; j < N; j++)
            if (j != p) c[j] -= f * __shfl_sync(0xffffffffu, c[j], p);
        c[p] = ncp;
    }
    if (lane < N) {
#pragma unroll
        for (int j = 0; j < N; j++) M[i * LD + j] = c[j] * dinv;
    }
    __syncwarp();
}

// ---------------- Kernel A0: input projection for LSTM layer 0 ----------------
__global__ void xw0_kernel(const float* __restrict__ a,
                           const float* __restrict__ Wih0,
                           const float* __restrict__ bih0,
                           const float* __restrict__ bhh0) {
    int idx = blockIdx.x * blockDim.x + threadIdx.x;
    if (idx >= BSZ * TT * GG) return;
    int j  = idx % GG;
    int bt = idx / GG;
    const float* ar = a + (size_t)bt * DA;
    const float* w  = Wih0 + j * DA;
    float s = bih0[j] + bhh0[j];
#pragma unroll
    for (int d = 0; d < DA; d++) s += ar[d] * w[d];
    g_xw0[idx] = s;
}

// ---------------- Kernel A1: sequential 2-layer LSTM + softmax ----------------
__global__ void lstm_kernel(const float* __restrict__ Whh0,
                            const float* __restrict__ Wih1,
                            const float* __restrict__ Whh1,
                            const float* __restrict__ bih1,
                            const float* __restrict__ bhh1) {
    __shared__ float whh0[GG][3], wih1[GG][3], whh1[GG][3], b1[GG];
    int tid = threadIdx.x;
    if (tid < 36) {
        whh0[tid / 3][tid % 3] = Whh0[tid];
        wih1[tid / 3][tid % 3] = Wih1[tid];
        whh1[tid / 3][tid % 3] = Whh1[tid];
    }
    if (tid < GG) b1[tid] = bih1[tid] + bhh1[tid];
    __syncthreads();

    int b = tid;
    if (b >= BSZ) return;
    float h0[3] = {0, 0, 0}, c0[3] = {0, 0, 0};
    float h1[3] = {0, 0, 0}, c1[3] = {0, 0, 0};
    const float* xw = g_xw0 + (size_t)b * TT * GG;
    float* al = g_alpha + (size_t)b * TT * KK;

    for (int t = 0; t < TT; t++) {
        float g[GG];
#pragma unroll
        for (int j = 0; j < GG; j++)
            g[j] = xw[t * GG + j] + whh0[j][0] * h0[0] + whh0[j][1] * h0[1] + whh0[j][2] * h0[2];
#pragma unroll
        for (int u = 0; u < 3; u++) {
            c0[u] = sigm(g[3 + u]) * c0[u] + sigm(g[u]) * tanhf(g[6 + u]);
            h0[u] = sigm(g[9 + u]) * tanhf(c0[u]);
        }
#pragma unroll
        for (int j = 0; j < GG; j++)
            g[j] = b1[j] + wih1[j][0] * h0[0] + wih1[j][1] * h0[1] + wih1[j][2] * h0[2]
                         + whh1[j][0] * h1[0] + whh1[j][1] * h1[1] + whh1[j][2] * h1[2];
#pragma unroll
        for (int u = 0; u < 3; u++) {
            c1[u] = sigm(g[3 + u]) * c1[u] + sigm(g[u]) * tanhf(g[6 + u]);
            h1[u] = sigm(g[9 + u]) * tanhf(c1[u]);
        }
        float m = fmaxf(h1[0], fmaxf(h1[1], h1[2]));
        float e0 = expf(h1[0] - m), e1 = expf(h1[1] - m), e2 = expf(h1[2] - m);
        float inv = 1.0f / (e0 + e1 + e2);
        al[t * KK + 0] = e0 * inv;
        al[t * KK + 1] = e1 * inv;
        al[t * KK + 2] = e2 * inv;
    }
}

// ---------------- Kernel B: forward Kalman filter (one CTA per batch, 256 thr) ---
__global__ void __launch_bounds__(256) fwd_kernel(const float* __restrict__ a,
                                                  const float* __restrict__ A,
                                                  const float* __restrict__ C,
                                                  const float* __restrict__ R,
                                                  const float* __restrict__ Q,
                                                  const float* __restrict__ mu0,
                                                  const float* __restrict__ sigma0) {
    const int b = blockIdx.x;
    const int tid = threadIdx.x;
    const int i8 = tid >> 3;            // 0..31
    const int q4 = (tid & 7) * 4;       // 0,4,...,28

    __shared__ __align__(16) float sAt[DZ][36], sAtT[DZ][36];
    __shared__ __align__(16) float sCt[DA][36];
    __shared__ __align__(16) float sCtT[DZ][20];
    __shared__ __align__(16) float sSigP[DZ][36], sSigN[DZ][36], sT[DZ][36], sQ[DZ][36];
    __shared__ __align__(16) float sM1[DZ][20], sKg[DZ][20];
    __shared__ __align__(16) float sS[DA][20];     // S, then S^{-1} in place
    __shared__ float sR[DA][17];
    __shared__ float smu_f[DZ], smu_p[DZ], sr[DA];

    // ---- init ----
    if (tid < DZ) { smu_f[tid] = mu0[tid]; smu_p[tid] = mu0[tid]; }
    {
        int e = tid * 4, ii = e >> 5, jj = e & 31;
        float4 s0 = ((const float4*)sigma0)[tid];
        *(float4*)&sSigP[ii][jj] = s0;
        float4 q0 = ((const float4*)Q)[tid];
        *(float4*)&sQ[ii][jj] = q0;
        sR[tid >> 4][tid & 15] = R[tid];
    }
    __syncthreads();

    for (int t = 0; t < TT; t++) {
        // P0: mixing (alpha via direct global loads, broadcast through L2)
        const size_t abase = ((size_t)b * TT + t) * KK;
        const float a0 = g_alpha[abase + 0];
        const float a1 = g_alpha[abase + 1];
        const float a2 = g_alpha[abase + 2];
        {
            const float4* A0 = (const float4*)A + (size_t)t * 256;
            const float4* A1 = A0 + (size_t)TT * 256;
            const float4* A2 = A1 + (size_t)TT * 256;
            float4 v0 = A0[tid], v1 = A1[tid], v2 = A2[tid];
            float4 m;
            m.x = a0 * v0.x + a1 * v1.x + a2 * v2.x;
            m.y = a0 * v0.y + a1 * v1.y + a2 * v2.y;
            m.z = a0 * v0.z + a1 * v1.z + a2 * v2.z;
            m.w = a0 * v0.w + a1 * v1.w + a2 * v2.w;
            int e = tid * 4, ii = e >> 5, jj = e & 31;
            *(float4*)&sAt[ii][jj] = m;
            sAtT[jj + 0][ii] = m.x; sAtT[jj + 1][ii] = m.y;
            sAtT[jj + 2][ii] = m.z; sAtT[jj + 3][ii] = m.w;
            if (tid < 128) {
                const float4* C0 = (const float4*)C + (size_t)t * 128;
                const float4* C1 = C0 + (size_t)TT * 128;
                const float4* C2 = C1 + (size_t)TT * 128;
                float4 w0 = C0[tid], w1 = C1[tid], w2 = C2[tid];
                float4 c;
                c.x = a0 * w0.x + a1 * w1.x + a2 * w2.x;
                c.y = a0 * w0.y + a1 * w1.y + a2 * w2.y;
                c.z = a0 * w0.z + a1 * w1.z + a2 * w2.z;
                c.w = a0 * w0.w + a1 * w1.w + a2 * w2.w;
                int ec = tid * 4, ic = ec >> 5, jc = ec & 31;
                *(float4*)&sCt[ic][jc] = c;
                sCtT[jc + 0][ic] = c.x; sCtT[jc + 1][ic] = c.y;
                sCtT[jc + 2][ic] = c.z; sCtT[jc + 3][ic] = c.w;
            }
        }
        __syncthreads();

        // P1: r = a - Ct mu_f ; M1 = sigP * CtT  (32x16)
        if (tid < DA) {
            float s = a[((size_t)b * TT + t) * DA + tid];
#pragma unroll
            for (int j = 0; j < DZ; j++) s -= sCt[tid][j] * smu_f[j];
            sr[tid] = s;
        }
        {
            int jj = (tid & 7) * 2;
            float s0 = 0.f, s1 = 0.f;
#pragma unroll
            for (int k = 0; k < DZ; k++) {
                float av = sSigP[i8][k];
                s0 += av * sCtT[k][jj];
                s1 += av * sCtT[k][jj + 1];
            }
            sM1[i8][jj] = s0; sM1[i8][jj + 1] = s1;
        }
        __syncthreads();

        // P2: S = Ct*M1 + R
        {
            int i = tid >> 4, j = tid & 15;
            float s = sR[i][j];
#pragma unroll
            for (int k = 0; k < DZ; k++) s += sCt[i][k] * sM1[k][j];
            sS[i][j] = s;
        }
        __syncthreads();

        // GJ16: warp 0 inverts S in place (registers + shuffles, 0 barriers)
        if (tid < 32) warp_gj_reg<DA, 20>(&sS[0][0], tid);
        __syncthreads();

        // Kg = M1 * Sinv
        {
            int jj = (tid & 7) * 2;
            float s0 = 0.f, s1 = 0.f;
#pragma unroll
            for (int k = 0; k < DA; k++) {
                float av = sM1[i8][k];
                s0 += av * sS[k][jj];
                s1 += av * sS[k][jj + 1];
            }
            sKg[i8][jj] = s0; sKg[i8][jj + 1] = s1;
        }
        __syncthreads();

        // T1 = Kg * Ct (32x32, K=16)
        {
            float4 acc = make_float4(0, 0, 0, 0);
#pragma unroll
            for (int k = 0; k < DA; k++) {
                float av = sKg[i8][k];
                float4 bv = *(const float4*)&sCt[k][q4];
                acc.x += av * bv.x; acc.y += av * bv.y;
                acc.z += av * bv.z; acc.w += av * bv.w;
            }
            *(float4*)&sT[i8][q4] = acc;
        }
        __syncthreads();

        const size_t sb = (size_t)t * BSZ + b;

        // P: signew = sigP - T1*sigP ; mu_new -> smu_f, g_muf
        {
            float4 acc = *(const float4*)&sSigP[i8][q4];
#pragma unroll
            for (int k = 0; k < DZ; k++) {
                float av = sT[i8][k];
                float4 bv = *(const float4*)&sSigP[k][q4];
                acc.x -= av * bv.x; acc.y -= av * bv.y;
                acc.z -= av * bv.z; acc.w -= av * bv.w;
            }
            *(float4*)&sSigN[i8][q4] = acc;
            *(float4*)&g_sigf[sb * (DZ * DZ) + i8 * DZ + q4] = acc;
        }
        if (tid < DZ) {
            float s = smu_p[tid];
#pragma unroll
            for (int j = 0; j < DA; j++) s += sKg[tid][j] * sr[j];
            smu_f[tid] = s;
            g_muf[sb * DZ + tid] = s;
        }
        __syncthreads();

        // P: T2 = At*signew ; mu_p = At*mu_new
        {
            float4 acc = make_float4(0, 0, 0, 0);
#pragma unroll
            for (int k = 0; k < DZ; k++) {
                float av = sAt[i8][k];
                float4 bv = *(const float4*)&sSigN[k][q4];
                acc.x += av * bv.x; acc.y += av * bv.y;
                acc.z += av * bv.z; acc.w += av * bv.w;
            }
            *(float4*)&sT[i8][q4] = acc;
        }
        if (tid < DZ) {
            float s = 0.f;
#pragma unroll
            for (int j = 0; j < DZ; j++) s += sAt[tid][j] * smu_f[j];
            smu_p[tid] = s;
            g_mup[sb * DZ + tid] = s;
        }
        __syncthreads();

        // P: sigp = T2*At^T + Q
        {
            float4 acc = *(const float4*)&sQ[i8][q4];
#pragma unroll
            for (int k = 0; k < DZ; k++) {
                float av = sT[i8][k];
                float4 bv = *(const float4*)&sAtT[k][q4];
                acc.x += av * bv.x; acc.y += av * bv.y;
                acc.z += av * bv.z; acc.w += av * bv.w;
            }
            *(float4*)&sSigP[i8][q4] = acc;
            *(float4*)&g_sigp[sb * (DZ * DZ) + i8 * DZ + q4] = acc;
        }
        __syncthreads();
    }
}

// ---------------- Kernel C: RTS backward smoother (one CTA per batch, 256 thr) ---
__global__ void __launch_bounds__(256) bwd_kernel(const float* __restrict__ A,
                                                  float* __restrict__ out) {
    const int b = blockIdx.x;
    const int tid = threadIdx.x;
    const int i8 = tid >> 3;
    const int q4 = (tid & 7) * 4;

    __shared__ __align__(16) float sAT[DZ][36];
    __shared__ __align__(16) float sSigF[DZ][36], sSigNc[DZ][36], sD[DZ][36];
    __shared__ __align__(16) float sU[DZ][36], sJ[DZ][36];
    __shared__ __align__(16) float sP[DZ][36];    // sig_p, then inverse in place
    __shared__ float sMuN[DZ], sMuD[DZ];

    // init t = T-1: smoothed == filtered
    {
        size_t sb = ((size_t)(TT - 1) * BSZ + b);
        size_t ob = ((size_t)b * TT + (TT - 1)) * (DZ + DZ * DZ);
        int e = tid * 4, ii = e >> 5, jj = e & 31;
        float4 v = ((const float4*)(g_sigf + sb * (DZ * DZ)))[tid];
        *(float4*)&sSigNc[ii][jj] = v;
        *(float4*)&out[ob + DZ + e] = v;
        if (tid < DZ) {
            float m = g_muf[sb * DZ + tid];
            sMuN[tid] = m;
            out[ob + tid] = m;
        }
    }
    __syncthreads();

    for (int t = TT - 2; t >= 0; t--) {
        const size_t sb = (size_t)t * BSZ + b;
        const size_t abase = ((size_t)b * TT + (t + 1)) * KK;
        const float a0 = g_alpha[abase + 0];
        const float a1 = g_alpha[abase + 1];
        const float a2 = g_alpha[abase + 2];

        // P0: mix A^T, load sigF, sigP, D = sigN - sigp, muD
        {
            const float4* A0 = (const float4*)A + (size_t)(t + 1) * 256;
            const float4* A1 = A0 + (size_t)TT * 256;
            const float4* A2 = A1 + (size_t)TT * 256;
            float4 v0 = A0[tid], v1 = A1[tid], v2 = A2[tid];
            int e = tid * 4, ii = e >> 5, jj = e & 31;
            sAT[jj + 0][ii] = a0 * v0.x + a1 * v1.x + a2 * v2.x;
            sAT[jj + 1][ii] = a0 * v0.y + a1 * v1.y + a2 * v2.y;
            sAT[jj + 2][ii] = a0 * v0.z + a1 * v1.z + a2 * v2.z;
            sAT[jj + 3][ii] = a0 * v0.w + a1 * v1.w + a2 * v2.w;

            float4 sf = ((const float4*)(g_sigf + sb * (DZ * DZ)))[tid];
            *(float4*)&sSigF[ii][jj] = sf;
            float4 sp = ((const float4*)(g_sigp + sb * (DZ * DZ)))[tid];
            *(float4*)&sP[ii][jj] = sp;
            float4 d;
            d.x = sSigNc[ii][jj + 0] - sp.x;
            d.y = sSigNc[ii][jj + 1] - sp.y;
            d.z = sSigNc[ii][jj + 2] - sp.z;
            d.w = sSigNc[ii][jj + 3] - sp.w;
            *(float4*)&sD[ii][jj] = d;
            if (tid < DZ) sMuD[tid] = sMuN[tid] - g_mup[sb * DZ + tid];
        }
        __syncthreads();

        // GJ32: warp 0 inverts sigP in place (registers + shuffles, 0 barriers)
        if (tid < 32) warp_gj_reg<DZ, 36>(&sP[0][0], tid);
        __syncthreads();

        // P1: U = sigF * A^T
        {
            float4 acc = make_float4(0, 0, 0, 0);
#pragma unroll
            for (int k = 0; k < DZ; k++) {
                float av = sSigF[i8][k];
                float4 bv = *(const float4*)&sAT[k][q4];
                acc.x += av * bv.x; acc.y += av * bv.y;
                acc.z += av * bv.z; acc.w += av * bv.w;
            }
            *(float4*)&sU[i8][q4] = acc;
        }
        __syncthreads();

        // J = U * Pinv (Pinv now in sP)
        {
            float4 acc = make_float4(0, 0, 0, 0);
#pragma unroll
            for (int k = 0; k < DZ; k++) {
                float av = sU[i8][k];
                float4 bv = *(const float4*)&sP[k][q4];
                acc.x += av * bv.x; acc.y += av * bv.y;
                acc.z += av * bv.z; acc.w += av * bv.w;
            }
            *(float4*)&sJ[i8][q4] = acc;
        }
        __syncthreads();

        // outputs + carry update
        {
            const size_t ob = ((size_t)b * TT + t) * (DZ + DZ * DZ);
            float4 acc = *(const float4*)&sSigF[i8][q4];
#pragma unroll
            for (int k = 0; k < DZ; k++) {
                float av = sJ[i8][k];
                float4 bv = *(const float4*)&sD[k][q4];
                acc.x += av * bv.x; acc.y += av * bv.y;
                acc.z += av * bv.z; acc.w += av * bv.w;
            }
            *(float4*)&sSigNc[i8][q4] = acc;
            *(float4*)&out[ob + DZ + i8 * DZ + q4] = acc;
            if (tid < DZ) {
                float s = g_muf[sb * DZ + tid];
#pragma unroll
                for (int k = 0; k < DZ; k++) s += sJ[tid][k] * sMuD[k];
                sMuN[tid] = s;
                out[ob + tid] = s;
            }
        }
        __syncthreads();
    }
}

// ---------------- launch ----------------
extern "C" void kernel_launch(void* const* d_in, const int* in_sizes, int n_in,
                              void* d_out, int out_size) {
    const float* a      = (const float*)d_in[0];
    const float* A      = (const float*)d_in[1];
    const float* C      = (const float*)d_in[2];
    const float* R      = (const float*)d_in[3];
    const float* Q      = (const float*)d_in[4];
    const float* mu0    = (const float*)d_in[5];
    const float* sigma0 = (const float*)d_in[6];
    const float* Wih0   = (const float*)d_in[7];
    const float* Whh0   = (const float*)d_in[8];
    const float* bih0   = (const float*)d_in[9];
    const float* bhh0   = (const float*)d_in[10];
    const float* Wih1   = (const float*)d_in[11];
    const float* Whh1   = (const float*)d_in[12];
    const float* bih1   = (const float*)d_in[13];
    const float* bhh1   = (const float*)d_in[14];
    float* out = (float*)d_out;

    int n0 = BSZ * TT * GG;
    xw0_kernel<<<(n0 + 255) / 256, 256>>>(a, Wih0, bih0, bhh0);
    lstm_kernel<<<1, 64>>>(Whh0, Wih1, Whh1, bih1, bhh1);
    fwd_kernel<<<BSZ, 256>>>(a, A, C, R, Q, mu0, sigma0);
    bwd_kernel<<<BSZ, 256>>>(A, out);
}